// round 3
// baseline (speedup 1.0000x reference)
#include <cuda_runtime.h>
#include <cuda_bf16.h>

#define NCLUST 256
#define NPT    128
#define NEDGE  1024
#define VS     32
#define VOXN   (VS*VS*VS)   // 32768

// Scratch (device globals — no runtime allocation allowed)
__device__ float g_cvox[NCLUST * VOXN];              // 32 MB
__device__ float g_c1[NEDGE * 16 * 16 * 16 * 16];    // 268 MB
__device__ float g_c2[NEDGE * 32 * 8 * 8 * 8];       // 67 MB
__device__ int   g_eidx_is_i64;
__device__ int   g_mask_is_u8;

// ---------------------------------------------------------------------------
// Kernel D: dtype layout detection (in-bounds under every candidate layout)
// ---------------------------------------------------------------------------
__global__ void detect_kernel(const int* __restrict__ eidx_w,
                              const unsigned int* __restrict__ mask_w,
                              int E, int maskWords)
{
    __shared__ int oddNZ, bigW;
    if (threadIdx.x == 0) { oddNZ = 0; bigW = 0; }
    __syncthreads();
    for (int i = threadIdx.x; i < E; i += blockDim.x)
        if (eidx_w[2 * i + 1] != 0) atomicOr(&oddNZ, 1);
    for (int i = threadIdx.x; i < maskWords; i += blockDim.x)
        if (mask_w[i] > 1u) atomicOr(&bigW, 1);
    __syncthreads();
    if (threadIdx.x == 0) {
        g_eidx_is_i64 = (oddNZ == 0) ? 1 : 0;   // int64 -> high words all 0
        g_mask_is_u8  = bigW;                   // 0x01010101-style words -> bytes
    }
}

// ---------------------------------------------------------------------------
// Kernel 0: per-cluster fractional-overlap voxelization (256 blocks x 256 thr)
// ---------------------------------------------------------------------------
__global__ __launch_bounds__(256) void vox_kernel(
    const float* __restrict__ data,
    const int* __restrict__ clusts,
    const void* __restrict__ cmask)
{
    const int c = blockIdx.x;
    const int t = threadIdx.x;

    __shared__ __align__(16) float ovy[NPT * VS];     // 16 KB
    __shared__ __align__(16) float ovz[NPT * VS];     // 16 KB
    __shared__ __align__(16) float sw[NPT];
    __shared__ __align__(16) float svx[NPT];
    __shared__ __align__(16) float spx[NPT], spy[NPT], spz[NPT];
    __shared__ __align__(16) float red[6 * NPT];

    const int mask_u8 = g_mask_is_u8;

    if (t < NPT) {
        int idx = clusts[c * NPT + t];
        int m;
        if (mask_u8) m = ((const unsigned char*)cmask)[c * NPT + t];
        else         m = ((const int*)cmask)[c * NPT + t];
        float x = data[idx * 5 + 0];
        float y = data[idx * 5 + 1];
        float z = data[idx * 5 + 2];
        float v = data[idx * 5 + 4];
        spx[t] = x; spy[t] = y; spz[t] = z;
        sw[t]  = m ? v : 0.0f;
        red[0*NPT + t] = m ? x :  1e9f;
        red[1*NPT + t] = m ? y :  1e9f;
        red[2*NPT + t] = m ? z :  1e9f;
        red[3*NPT + t] = m ? x : -1e9f;
        red[4*NPT + t] = m ? y : -1e9f;
        red[5*NPT + t] = m ? z : -1e9f;
    }
    __syncthreads();
    for (int s = 64; s > 0; s >>= 1) {
        if (t < s) {
            red[0*NPT + t] = fminf(red[0*NPT + t], red[0*NPT + t + s]);
            red[1*NPT + t] = fminf(red[1*NPT + t], red[1*NPT + t + s]);
            red[2*NPT + t] = fminf(red[2*NPT + t], red[2*NPT + t + s]);
            red[3*NPT + t] = fmaxf(red[3*NPT + t], red[3*NPT + t + s]);
            red[4*NPT + t] = fmaxf(red[4*NPT + t], red[4*NPT + t + s]);
            red[5*NPT + t] = fmaxf(red[5*NPT + t], red[5*NPT + t + s]);
        }
        __syncthreads();
    }
    const float minx = red[0], miny = red[NPT], minz = red[2*NPT];
    const float rx = red[3*NPT] - minx;
    const float ry = red[4*NPT] - miny;
    const float rz = red[5*NPT] - minz;
    const float mr = fmaxf(rx, fmaxf(ry, rz)) + 1.0f;
    const float gs  = 1.0f / mr;
    const float rgs = mr;               // 1/gs: overlap is divided by gs
    const float ns  = 1.0f / (float)VS;

    {
        int p    = t & (NPT - 1);
        int half = t >> 7;
        float vy = (spy[p] - miny - ry * 0.5f - 0.5f) * gs + 0.5f;
        float vz = (spz[p] - minz - rz * 0.5f - 0.5f) * gs + 0.5f;
        for (int b = half * 16; b < half * 16 + 16; ++b) {
            float lo = (float)b * ns;
            float oy = fminf(vy + gs, lo + ns) - fmaxf(vy, lo);
            float oz = fminf(vz + gs, lo + ns) - fmaxf(vz, lo);
            ovy[p * VS + b] = fmaxf(oy, 0.0f) * rgs;
            ovz[p * VS + b] = fmaxf(oz, 0.0f) * rgs;
        }
        if (t < NPT)
            svx[t] = (spx[t] - minx - rx * 0.5f - 0.5f) * gs + 0.5f;
    }
    __syncthreads();

    float* outp = g_cvox + (size_t)c * VOXN;
    for (int pass = 0; pass < 4; ++pass) {
        int jk = t + pass * 256;
        int j = jk >> 5, k = jk & 31;     // j uniform per warp, k = lane
        float acc[VS];
#pragma unroll
        for (int i = 0; i < VS; ++i) acc[i] = 0.0f;
        for (int p = 0; p < NPT; ++p) {
            float ty = sw[p] * ovy[p * VS + j];     // uniform across warp
            if (ty != 0.0f) {                       // uniform branch, mostly skipped
                float tz = ty * ovz[p * VS + k];
                float vx = svx[p];
#pragma unroll
                for (int i = 0; i < VS; ++i) {
                    float lo = (float)i * ns;
                    float ox = fminf(vx + gs, lo + ns) - fmaxf(vx, lo);
                    ox = fmaxf(ox, 0.0f) * rgs;
                    acc[i] += ox * tz;
                }
            }
        }
#pragma unroll
        for (int i = 0; i < VS; ++i)
            outp[i * (VS * VS) + jk] = acc[i];
    }
}

// ---------------------------------------------------------------------------
// Kernel 1: conv1 (1->16ch, 3^3, stride2) fused with vox[ei]+vox[ej]
// grid = E*8 (8 spatial tiles of 8^3 per edge), 512 threads
// ---------------------------------------------------------------------------
__global__ __launch_bounds__(512) void conv1_kernel(
    const int* __restrict__ eidx,
    const float* __restrict__ W1,
    const float* __restrict__ b1,
    int E, int C)
{
    __shared__ __align__(16) float s_in[17 * 17 * 17];
    __shared__ __align__(16) float s_w[16 * 27];
    __shared__ __align__(16) float s_b[16];

    const int blk  = blockIdx.x;
    const int e    = blk >> 3;
    const int tile = blk & 7;
    const int tz = (tile >> 2) & 1, tyy = (tile >> 1) & 1, tx = tile & 1;
    const int t = threadIdx.x;

    int ca, cb;
    if (g_eidx_is_i64) { ca = eidx[2 * e]; cb = eidx[2 * (E + e)]; }
    else               { ca = eidx[e];     cb = eidx[E + e];       }
    ca = min(max(ca, 0), C - 1);
    cb = min(max(cb, 0), C - 1);
    const float* __restrict__ A = g_cvox + (size_t)ca * VOXN;
    const float* __restrict__ B = g_cvox + (size_t)cb * VOXN;
    const int z0 = tz * 16, y0 = tyy * 16, x0 = tx * 16;

    for (int i = t; i < 17 * 17 * 17; i += 512) {
        int z = i / 289, r = i % 289, y = r / 17, x = r % 17;
        int gz = z0 + z, gy = y0 + y, gx = x0 + x;
        float v = 0.0f;
        if (gz < 32 && gy < 32 && gx < 32) {
            int o = (gz * 32 + gy) * 32 + gx;
            v = A[o] + B[o];
        }
        s_in[i] = v;
    }
    if (t < 432) s_w[t] = W1[t];
    if (t < 16)  s_b[t] = b1[t];
    __syncthreads();

    const int x = t & 7, y = (t >> 3) & 7, z = t >> 6;
    float acc[16];
#pragma unroll
    for (int oc = 0; oc < 16; ++oc) acc[oc] = 0.0f;
    const int ib = (2 * z) * 289 + (2 * y) * 17 + 2 * x;
#pragma unroll
    for (int dz = 0; dz < 3; ++dz)
#pragma unroll
        for (int dy = 0; dy < 3; ++dy)
#pragma unroll
            for (int dx = 0; dx < 3; ++dx) {
                float v = s_in[ib + dz * 289 + dy * 17 + dx];
                const int tap = (dz * 3 + dy) * 3 + dx;
#pragma unroll
                for (int oc = 0; oc < 16; ++oc)
                    acc[oc] += v * s_w[oc * 27 + tap];
            }
    const int oz = tz * 8 + z, oy = tyy * 8 + y, ox = tx * 8 + x;
    float* outp = g_c1 + (size_t)e * 16 * 4096;
#pragma unroll
    for (int oc = 0; oc < 16; ++oc)
        outp[oc * 4096 + oz * 256 + oy * 16 + ox] = fmaxf(acc[oc] + s_b[oc], 0.0f);
}

// ---------------------------------------------------------------------------
// Kernel 2: conv2 (16->32ch, 3^3, stride2). 1024 blocks x 512 threads.
// Thread = 8 oc x 4 spatial register tile; weights smem-transposed [tap][oc].
// ---------------------------------------------------------------------------
__global__ __launch_bounds__(512) void conv2_kernel(
    const float* __restrict__ W2,
    const float* __restrict__ b2)
{
    __shared__ __align__(16) float s_in[17 * 17 * 17];   // 4913 floats
    __shared__ __align__(16) float s_w[27 * 32];         // [tap][oc] — LDS.128
    __shared__ __align__(16) float s_b[32];

    const int e = blockIdx.x;
    const int t = threadIdx.x;
    const int og = t >> 7;      // 4 groups of 8 output channels
    const int sg = t & 127;     // 4 spatial points each

    int ibq[4], sq[4];
#pragma unroll
    for (int q = 0; q < 4; ++q) {
        int s = sg * 4 + q;
        sq[q] = s;
        int x = s & 7, y = (s >> 3) & 7, z = s >> 6;
        ibq[q] = (2 * z) * 289 + (2 * y) * 17 + 2 * x;
    }
    if (t < 32) s_b[t] = b2[t];

    float acc[8][4];
#pragma unroll
    for (int j = 0; j < 8; ++j)
#pragma unroll
        for (int q = 0; q < 4; ++q) acc[j][q] = 0.0f;

    for (int ic = 0; ic < 16; ++ic) {
        __syncthreads();
        const float* __restrict__ src = g_c1 + ((size_t)e * 16 + ic) * 4096;
        for (int i = t; i < 17 * 17 * 17; i += 512) {
            int z = i / 289, r = i % 289, y = r / 17, x = r % 17;
            s_in[i] = (z < 16 && y < 16 && x < 16) ? src[(z << 8) + (y << 4) + x] : 0.0f;
        }
        for (int i = t; i < 27 * 32; i += 512) {
            int tap = i >> 5, oc = i & 31;
            s_w[i] = W2[(oc * 16 + ic) * 27 + tap];
        }
        __syncthreads();
#pragma unroll
        for (int dz = 0; dz < 3; ++dz)
#pragma unroll
            for (int dy = 0; dy < 3; ++dy)
#pragma unroll
                for (int dx = 0; dx < 3; ++dx) {
                    const int tap = (dz * 3 + dy) * 3 + dx;
                    const float4 w0 = *(const float4*)&s_w[tap * 32 + og * 8];
                    const float4 w1 = *(const float4*)&s_w[tap * 32 + og * 8 + 4];
                    const int off = dz * 289 + dy * 17 + dx;
#pragma unroll
                    for (int q = 0; q < 4; ++q) {
                        float v = s_in[ibq[q] + off];
                        acc[0][q] += v * w0.x;
                        acc[1][q] += v * w0.y;
                        acc[2][q] += v * w0.z;
                        acc[3][q] += v * w0.w;
                        acc[4][q] += v * w1.x;
                        acc[5][q] += v * w1.y;
                        acc[6][q] += v * w1.z;
                        acc[7][q] += v * w1.w;
                    }
                }
    }
    float* outp = g_c2 + (size_t)e * 32 * 512;
#pragma unroll
    for (int j = 0; j < 8; ++j) {
        const int oc = og * 8 + j;
        const float bb = s_b[oc];
#pragma unroll
        for (int q = 0; q < 4; ++q)
            outp[oc * 512 + sq[q]] = fmaxf(acc[j][q] + bb, 0.0f);
    }
}

// ---------------------------------------------------------------------------
// Kernel 3: conv3 (32->64ch) + relu + global mean-pool + FC(64x64)
// 1024 blocks x 512 threads (thread = 8 oc x 1 of 64 spatial points)
// ---------------------------------------------------------------------------
__global__ __launch_bounds__(512) void conv3_kernel(
    const float* __restrict__ W3,
    const float* __restrict__ b3,
    const float* __restrict__ Wfc,
    const float* __restrict__ bfc,
    float* __restrict__ out)
{
    __shared__ __align__(16) float s_in[9 * 9 * 9];      // 729 floats
    __shared__ __align__(16) float s_w[27 * 64];         // [tap][oc] — LDS.128
    __shared__ __align__(16) float s_pool[64 * 65];
    __shared__ __align__(16) float s_pooled[64];

    const int e = blockIdx.x;
    const int t = threadIdx.x;
    const int og = t >> 6;     // 8 groups of 8 oc
    const int s  = t & 63;
    const int x = s & 3, y = (s >> 2) & 3, z = s >> 4;
    const int ib = (2 * z) * 81 + (2 * y) * 9 + 2 * x;

    float acc[8];
#pragma unroll
    for (int j = 0; j < 8; ++j) acc[j] = 0.0f;

    for (int ic = 0; ic < 32; ++ic) {
        __syncthreads();
        const float* __restrict__ src = g_c2 + ((size_t)e * 32 + ic) * 512;
        for (int i = t; i < 729; i += 512) {
            int zz = i / 81, r = i % 81, yy = r / 9, xx = r % 9;
            s_in[i] = (zz < 8 && yy < 8 && xx < 8) ? src[(zz << 6) + (yy << 3) + xx] : 0.0f;
        }
        for (int i = t; i < 27 * 64; i += 512) {
            int tap = i >> 6, oc = i & 63;
            s_w[i] = W3[(oc * 32 + ic) * 27 + tap];
        }
        __syncthreads();
#pragma unroll
        for (int dz = 0; dz < 3; ++dz)
#pragma unroll
            for (int dy = 0; dy < 3; ++dy)
#pragma unroll
                for (int dx = 0; dx < 3; ++dx) {
                    const int tap = (dz * 3 + dy) * 3 + dx;
                    const float4 w0 = *(const float4*)&s_w[tap * 64 + og * 8];
                    const float4 w1 = *(const float4*)&s_w[tap * 64 + og * 8 + 4];
                    const float v = s_in[ib + dz * 81 + dy * 9 + dx];
                    acc[0] += v * w0.x;
                    acc[1] += v * w0.y;
                    acc[2] += v * w0.z;
                    acc[3] += v * w0.w;
                    acc[4] += v * w1.x;
                    acc[5] += v * w1.y;
                    acc[6] += v * w1.z;
                    acc[7] += v * w1.w;
                }
    }
    __syncthreads();
#pragma unroll
    for (int j = 0; j < 8; ++j)
        s_pool[s * 65 + og * 8 + j] = fmaxf(acc[j] + __ldg(&b3[og * 8 + j]), 0.0f);
    __syncthreads();
    if (t < 64) {
        float sum = 0.0f;
#pragma unroll 8
        for (int sp = 0; sp < 64; ++sp) sum += s_pool[sp * 65 + t];
        s_pooled[t] = sum * (1.0f / 64.0f);
    }
    __syncthreads();
    if (t < 64) {
        float r = bfc[t];
#pragma unroll 8
        for (int ic = 0; ic < 64; ++ic)
            r += s_pooled[ic] * __ldg(&Wfc[ic * 64 + t]);
        out[e * 64 + t] = r;
    }
}

// ---------------------------------------------------------------------------
extern "C" void kernel_launch(void* const* d_in, const int* in_sizes, int n_in,
                              void* d_out, int out_size)
{
    const float* data   = (const float*)d_in[0];
    const int*   clusts = (const int*)d_in[1];
    const void*  cmask  = d_in[2];
    const int*   eidx   = (const int*)d_in[3];
    const float* W1     = (const float*)d_in[4];
    const float* b1     = (const float*)d_in[5];
    const float* W2     = (const float*)d_in[6];
    const float* b2     = (const float*)d_in[7];
    const float* W3     = (const float*)d_in[8];
    const float* b3     = (const float*)d_in[9];
    const float* Wfc    = (const float*)d_in[10];
    const float* bfc    = (const float*)d_in[11];
    float*       out    = (float*)d_out;

    const int C = in_sizes[1] / NPT;   // 256
    const int E = in_sizes[3] / 2;     // 1024
    const int maskWords = in_sizes[2] / 4;

    detect_kernel<<<1, 256>>>(eidx, (const unsigned int*)cmask, E, maskWords);
    vox_kernel<<<C, 256>>>(data, clusts, cmask);
    conv1_kernel<<<E * 8, 512>>>(eidx, W1, b1, E, C);
    conv2_kernel<<<E, 512>>>(W2, b2);
    conv3_kernel<<<E, 512>>>(W3, b3, Wfc, bfc, out);
}

// round 4
// speedup vs baseline: 1.3231x; 1.3231x over previous
#include <cuda_runtime.h>
#include <cuda_bf16.h>

#define NCLUST 256
#define NPT    128
#define NEDGE  1024
#define VS     32
#define VOXN   (VS*VS*VS)   // 32768

typedef unsigned long long ull;

// packed fp32x2 helpers (FFMA2 — only reachable via PTX)
__device__ __forceinline__ ull pk2(float lo, float hi) {
    ull r; asm("mov.b64 %0, {%1,%2};" : "=l"(r) : "f"(lo), "f"(hi)); return r;
}
__device__ __forceinline__ void fma2(ull& d, ull a, ull b) {
    asm("fma.rn.f32x2 %0, %1, %2, %0;" : "+l"(d) : "l"(a), "l"(b));
}
__device__ __forceinline__ float2 upk2(ull v) {
    float2 r; asm("mov.b64 {%0,%1}, %2;" : "=f"(r.x), "=f"(r.y) : "l"(v)); return r;
}

// Scratch (device globals — no runtime allocation allowed)
__device__ float g_cvox[NCLUST * VOXN];              // 32 MB
__device__ float g_c1[NEDGE * 16 * 16 * 16 * 16];    // 268 MB
__device__ float g_c2[NEDGE * 32 * 8 * 8 * 8];       // 67 MB
__device__ int   g_eidx_is_i64;
__device__ int   g_mask_is_u8;

// ---------------------------------------------------------------------------
// Kernel D: dtype layout detection
// ---------------------------------------------------------------------------
__global__ void detect_kernel(const int* __restrict__ eidx_w,
                              const unsigned int* __restrict__ mask_w,
                              int E, int maskWords)
{
    __shared__ int oddNZ, bigW;
    if (threadIdx.x == 0) { oddNZ = 0; bigW = 0; }
    __syncthreads();
    for (int i = threadIdx.x; i < E; i += blockDim.x)
        if (eidx_w[2 * i + 1] != 0) atomicOr(&oddNZ, 1);
    for (int i = threadIdx.x; i < maskWords; i += blockDim.x)
        if (mask_w[i] > 1u) atomicOr(&bigW, 1);
    __syncthreads();
    if (threadIdx.x == 0) {
        g_eidx_is_i64 = (oddNZ == 0) ? 1 : 0;
        g_mask_is_u8  = bigW;
    }
}

// ---------------------------------------------------------------------------
// Kernel 0: per-cluster voxelization (unchanged — not the bottleneck)
// ---------------------------------------------------------------------------
__global__ __launch_bounds__(256) void vox_kernel(
    const float* __restrict__ data,
    const int* __restrict__ clusts,
    const void* __restrict__ cmask)
{
    const int c = blockIdx.x;
    const int t = threadIdx.x;

    __shared__ __align__(16) float ovy[NPT * VS];
    __shared__ __align__(16) float ovz[NPT * VS];
    __shared__ __align__(16) float sw[NPT];
    __shared__ __align__(16) float svx[NPT];
    __shared__ __align__(16) float spx[NPT], spy[NPT], spz[NPT];
    __shared__ __align__(16) float red[6 * NPT];

    const int mask_u8 = g_mask_is_u8;

    if (t < NPT) {
        int idx = clusts[c * NPT + t];
        int m;
        if (mask_u8) m = ((const unsigned char*)cmask)[c * NPT + t];
        else         m = ((const int*)cmask)[c * NPT + t];
        float x = data[idx * 5 + 0];
        float y = data[idx * 5 + 1];
        float z = data[idx * 5 + 2];
        float v = data[idx * 5 + 4];
        spx[t] = x; spy[t] = y; spz[t] = z;
        sw[t]  = m ? v : 0.0f;
        red[0*NPT + t] = m ? x :  1e9f;
        red[1*NPT + t] = m ? y :  1e9f;
        red[2*NPT + t] = m ? z :  1e9f;
        red[3*NPT + t] = m ? x : -1e9f;
        red[4*NPT + t] = m ? y : -1e9f;
        red[5*NPT + t] = m ? z : -1e9f;
    }
    __syncthreads();
    for (int s = 64; s > 0; s >>= 1) {
        if (t < s) {
            red[0*NPT + t] = fminf(red[0*NPT + t], red[0*NPT + t + s]);
            red[1*NPT + t] = fminf(red[1*NPT + t], red[1*NPT + t + s]);
            red[2*NPT + t] = fminf(red[2*NPT + t], red[2*NPT + t + s]);
            red[3*NPT + t] = fmaxf(red[3*NPT + t], red[3*NPT + t + s]);
            red[4*NPT + t] = fmaxf(red[4*NPT + t], red[4*NPT + t + s]);
            red[5*NPT + t] = fmaxf(red[5*NPT + t], red[5*NPT + t + s]);
        }
        __syncthreads();
    }
    const float minx = red[0], miny = red[NPT], minz = red[2*NPT];
    const float rx = red[3*NPT] - minx;
    const float ry = red[4*NPT] - miny;
    const float rz = red[5*NPT] - minz;
    const float mr = fmaxf(rx, fmaxf(ry, rz)) + 1.0f;
    const float gs  = 1.0f / mr;
    const float rgs = mr;
    const float ns  = 1.0f / (float)VS;

    {
        int p    = t & (NPT - 1);
        int half = t >> 7;
        float vy = (spy[p] - miny - ry * 0.5f - 0.5f) * gs + 0.5f;
        float vz = (spz[p] - minz - rz * 0.5f - 0.5f) * gs + 0.5f;
        for (int b = half * 16; b < half * 16 + 16; ++b) {
            float lo = (float)b * ns;
            float oy = fminf(vy + gs, lo + ns) - fmaxf(vy, lo);
            float oz = fminf(vz + gs, lo + ns) - fmaxf(vz, lo);
            ovy[p * VS + b] = fmaxf(oy, 0.0f) * rgs;
            ovz[p * VS + b] = fmaxf(oz, 0.0f) * rgs;
        }
        if (t < NPT)
            svx[t] = (spx[t] - minx - rx * 0.5f - 0.5f) * gs + 0.5f;
    }
    __syncthreads();

    float* outp = g_cvox + (size_t)c * VOXN;
    for (int pass = 0; pass < 4; ++pass) {
        int jk = t + pass * 256;
        int j = jk >> 5, k = jk & 31;
        float acc[VS];
#pragma unroll
        for (int i = 0; i < VS; ++i) acc[i] = 0.0f;
        for (int p = 0; p < NPT; ++p) {
            float ty = sw[p] * ovy[p * VS + j];
            if (ty != 0.0f) {
                float tz = ty * ovz[p * VS + k];
                float vx = svx[p];
#pragma unroll
                for (int i = 0; i < VS; ++i) {
                    float lo = (float)i * ns;
                    float ox = fminf(vx + gs, lo + ns) - fmaxf(vx, lo);
                    ox = fmaxf(ox, 0.0f) * rgs;
                    acc[i] += ox * tz;
                }
            }
        }
#pragma unroll
        for (int i = 0; i < VS; ++i)
            outp[i * (VS * VS) + jk] = acc[i];
    }
}

// ---------------------------------------------------------------------------
// Kernel 1: conv1 (1->16ch) fused with vox[ei]+vox[ej]. grid=E*8, 256 thr.
// Thread = 16oc (8 packed) x 2 spatial. Padded smem stride 20/340.
// ---------------------------------------------------------------------------
#define SD1 20
#define SD2 340           // 20*17
#define SIN_SZ (17*SD2)   // 5780

__global__ __launch_bounds__(256, 2) void conv1_kernel(
    const int* __restrict__ eidx,
    const float* __restrict__ W1,
    const float* __restrict__ b1,
    int E, int C)
{
    __shared__ __align__(16) float s_in[SIN_SZ];
    __shared__ __align__(16) float s_w[27 * 16];   // [tap][oc]
    __shared__ __align__(16) float s_b[16];

    const int blk  = blockIdx.x;
    const int e    = blk >> 3;
    const int tile = blk & 7;
    const int tz = (tile >> 2) & 1, tyy = (tile >> 1) & 1, tx = tile & 1;
    const int t = threadIdx.x;

    int ca, cb;
    if (g_eidx_is_i64) { ca = eidx[2 * e]; cb = eidx[2 * (E + e)]; }
    else               { ca = eidx[e];     cb = eidx[E + e];       }
    ca = min(max(ca, 0), C - 1);
    cb = min(max(cb, 0), C - 1);
    const float* __restrict__ A = g_cvox + (size_t)ca * VOXN;
    const float* __restrict__ B = g_cvox + (size_t)cb * VOXN;
    const int z0 = tz * 16, y0 = tyy * 16, x0 = tx * 16;

    for (int i = t; i < SIN_SZ; i += 256) s_in[i] = 0.0f;
    for (int i = t; i < 432; i += 256) {
        int oc = i / 27, tap = i % 27;
        s_w[tap * 16 + oc] = W1[i];
    }
    if (t < 16) s_b[t] = b1[t];
    __syncthreads();

    for (int i = t; i < 17 * 17 * 17; i += 256) {
        int z = i / 289, r = i % 289, y = r / 17, x = r % 17;
        int gz = z0 + z, gy = y0 + y, gx = x0 + x;
        if (gz < 32 && gy < 32 && gx < 32) {
            int o = (gz * 32 + gy) * 32 + gx;
            s_in[z * SD2 + y * SD1 + x] = A[o] + B[o];
        }
    }
    __syncthreads();

    const int sg = t & 63;                 // y*8 + x
    const int lx = sg & 7, ly = sg >> 3;
    const int zq = t >> 6;                 // 0..3 -> z = 2*zq + h
    const int laneoff = ly * 2 * SD1 + lx * 2;

    ull acc[2][8];
#pragma unroll
    for (int h = 0; h < 2; ++h)
#pragma unroll
        for (int m = 0; m < 8; ++m) acc[h][m] = 0ULL;

#pragma unroll
    for (int dz = 0; dz < 3; ++dz)
#pragma unroll
        for (int dy = 0; dy < 3; ++dy)
#pragma unroll
            for (int dx = 0; dx < 3; ++dx) {
                const int tap = (dz * 3 + dy) * 3 + dx;
                const ulonglong2 w01 = *(const ulonglong2*)&s_w[tap * 16];
                const ulonglong2 w23 = *(const ulonglong2*)&s_w[tap * 16 + 4];
                const ulonglong2 w45 = *(const ulonglong2*)&s_w[tap * 16 + 8];
                const ulonglong2 w67 = *(const ulonglong2*)&s_w[tap * 16 + 12];
                const int off = laneoff + dz * SD2 + dy * SD1 + dx;
#pragma unroll
                for (int h = 0; h < 2; ++h) {
                    float v = s_in[off + (zq * 2 + h) * 2 * SD2];
                    ull v2 = pk2(v, v);
                    fma2(acc[h][0], v2, w01.x);
                    fma2(acc[h][1], v2, w01.y);
                    fma2(acc[h][2], v2, w23.x);
                    fma2(acc[h][3], v2, w23.y);
                    fma2(acc[h][4], v2, w45.x);
                    fma2(acc[h][5], v2, w45.y);
                    fma2(acc[h][6], v2, w67.x);
                    fma2(acc[h][7], v2, w67.y);
                }
            }

    float* outp = g_c1 + (size_t)e * 16 * 4096;
#pragma unroll
    for (int h = 0; h < 2; ++h) {
        const int oz = tz * 8 + zq * 2 + h;
        const int oy = tyy * 8 + ly, ox = tx * 8 + lx;
        const int sp = oz * 256 + oy * 16 + ox;
#pragma unroll
        for (int m = 0; m < 8; ++m) {
            float2 p = upk2(acc[h][m]);
            outp[(2 * m)     * 4096 + sp] = fmaxf(p.x + s_b[2 * m],     0.0f);
            outp[(2 * m + 1) * 4096 + sp] = fmaxf(p.y + s_b[2 * m + 1], 0.0f);
        }
    }
}

// ---------------------------------------------------------------------------
// Kernel 2: conv2 (16->32ch). 1024 blocks x 256 thr, 2 CTAs/SM.
// Thread = 8oc (4 packed) x 8 spatial (z). Coalesced float4 fill.
// ---------------------------------------------------------------------------
__global__ __launch_bounds__(256, 2) void conv2_kernel(
    const float* __restrict__ W2,
    const float* __restrict__ b2)
{
    __shared__ __align__(16) float s_in[SIN_SZ];   // 23.1 KB
    __shared__ __align__(16) float s_w[27 * 32];   // [tap][oc]
    __shared__ __align__(16) float s_b[32];

    const int e = blockIdx.x;
    const int t = threadIdx.x;
    const int og = t >> 6;        // 0..3 (uniform per warp)
    const int sg = t & 63;        // y*8+x
    const int lx = sg & 7, ly = sg >> 3;
    const int laneoff = ly * 2 * SD1 + lx * 2;

    for (int i = t; i < SIN_SZ; i += 256) s_in[i] = 0.0f;   // pad written once
    if (t < 32) s_b[t] = b2[t];

    ull acc[4][8];
#pragma unroll
    for (int m = 0; m < 4; ++m)
#pragma unroll
        for (int q = 0; q < 8; ++q) acc[m][q] = 0ULL;

    for (int ic = 0; ic < 16; ++ic) {
        __syncthreads();
        const float4* __restrict__ src4 =
            (const float4*)(g_c1 + ((size_t)e * 16 + ic) * 4096);
        for (int i4 = t; i4 < 1024; i4 += 256) {           // coalesced
            float4 v = src4[i4];
            int i = i4 * 4;
            int x = i & 15, y = (i >> 4) & 15, z = i >> 8;
            *(float4*)&s_in[z * SD2 + y * SD1 + x] = v;
        }
        for (int i = t; i < 27 * 32; i += 256) {
            int tap = i >> 5, oc = i & 31;
            s_w[i] = W2[(oc * 16 + ic) * 27 + tap];
        }
        __syncthreads();
#pragma unroll
        for (int dz = 0; dz < 3; ++dz)
#pragma unroll
            for (int dy = 0; dy < 3; ++dy)
#pragma unroll
                for (int dx = 0; dx < 3; ++dx) {
                    const int tap = (dz * 3 + dy) * 3 + dx;
                    const ulonglong2 wa = *(const ulonglong2*)&s_w[tap * 32 + og * 8];
                    const ulonglong2 wb = *(const ulonglong2*)&s_w[tap * 32 + og * 8 + 4];
                    const int off = laneoff + dz * SD2 + dy * SD1 + dx;
#pragma unroll
                    for (int q = 0; q < 8; ++q) {
                        float v = s_in[off + q * 2 * SD2];
                        ull v2 = pk2(v, v);
                        fma2(acc[0][q], v2, wa.x);
                        fma2(acc[1][q], v2, wa.y);
                        fma2(acc[2][q], v2, wb.x);
                        fma2(acc[3][q], v2, wb.y);
                    }
                }
    }

    float* outp = g_c2 + (size_t)e * 32 * 512;
#pragma unroll
    for (int m = 0; m < 4; ++m) {
        const int oc0 = og * 8 + 2 * m;
        const float b0 = s_b[oc0], b1v = s_b[oc0 + 1];
#pragma unroll
        for (int q = 0; q < 8; ++q) {
            float2 p = upk2(acc[m][q]);
            const int sidx = q * 64 + sg;
            outp[oc0 * 512 + sidx]       = fmaxf(p.x + b0,  0.0f);
            outp[(oc0 + 1) * 512 + sidx] = fmaxf(p.y + b1v, 0.0f);
        }
    }
}

// ---------------------------------------------------------------------------
// Kernel 3: conv3 (32->64ch) + relu + mean-pool + FC. 1024 blocks x 512 thr.
// ---------------------------------------------------------------------------
#define C3S1 12
#define C3S2 108           // 12*9
#define C3SZ (9*C3S2)      // 972

__global__ __launch_bounds__(512) void conv3_kernel(
    const float* __restrict__ W3,
    const float* __restrict__ b3,
    const float* __restrict__ Wfc,
    const float* __restrict__ bfc,
    float* __restrict__ out)
{
    __shared__ __align__(16) float s_in[C3SZ];
    __shared__ __align__(16) float s_w[27 * 64];   // [tap][oc]
    __shared__ __align__(16) float s_pool[64 * 65];
    __shared__ __align__(16) float s_pooled[64];

    const int e = blockIdx.x;
    const int t = threadIdx.x;
    const int og = t >> 6;     // 0..7 (uniform per warp)
    const int s  = t & 63;
    const int lx = s & 3, ly = (s >> 2) & 3, lz = s >> 4;
    const int base = lz * 2 * C3S2 + ly * 2 * C3S1 + lx * 2;

    for (int i = t; i < C3SZ; i += 512) s_in[i] = 0.0f;

    ull acc[4];
#pragma unroll
    for (int m = 0; m < 4; ++m) acc[m] = 0ULL;

    for (int ic = 0; ic < 32; ++ic) {
        __syncthreads();
        const float4* __restrict__ src4 =
            (const float4*)(g_c2 + ((size_t)e * 32 + ic) * 512);
        if (t < 128) {
            float4 v = src4[t];
            int i = t * 4;
            int x = i & 7, y = (i >> 3) & 7, z = i >> 6;
            *(float4*)&s_in[z * C3S2 + y * C3S1 + x] = v;
        }
        for (int i = t; i < 27 * 64; i += 512) {
            int tap = i >> 6, oc = i & 63;
            s_w[i] = W3[(oc * 32 + ic) * 27 + tap];
        }
        __syncthreads();
#pragma unroll
        for (int dz = 0; dz < 3; ++dz)
#pragma unroll
            for (int dy = 0; dy < 3; ++dy)
#pragma unroll
                for (int dx = 0; dx < 3; ++dx) {
                    const int tap = (dz * 3 + dy) * 3 + dx;
                    const ulonglong2 wa = *(const ulonglong2*)&s_w[tap * 64 + og * 8];
                    const ulonglong2 wb = *(const ulonglong2*)&s_w[tap * 64 + og * 8 + 4];
                    const float v = s_in[base + dz * C3S2 + dy * C3S1 + dx];
                    ull v2 = pk2(v, v);
                    fma2(acc[0], v2, wa.x);
                    fma2(acc[1], v2, wa.y);
                    fma2(acc[2], v2, wb.x);
                    fma2(acc[3], v2, wb.y);
                }
    }
    __syncthreads();
#pragma unroll
    for (int m = 0; m < 4; ++m) {
        float2 p = upk2(acc[m]);
        const int oc0 = og * 8 + 2 * m;
        s_pool[s * 65 + oc0]     = fmaxf(p.x + __ldg(&b3[oc0]),     0.0f);
        s_pool[s * 65 + oc0 + 1] = fmaxf(p.y + __ldg(&b3[oc0 + 1]), 0.0f);
    }
    __syncthreads();
    if (t < 64) {
        float sum = 0.0f;
#pragma unroll 8
        for (int sp = 0; sp < 64; ++sp) sum += s_pool[sp * 65 + t];
        s_pooled[t] = sum * (1.0f / 64.0f);
    }
    __syncthreads();
    if (t < 64) {
        float r = bfc[t];
#pragma unroll 8
        for (int ic = 0; ic < 64; ++ic)
            r += s_pooled[ic] * __ldg(&Wfc[ic * 64 + t]);
        out[e * 64 + t] = r;
    }
}

// ---------------------------------------------------------------------------
extern "C" void kernel_launch(void* const* d_in, const int* in_sizes, int n_in,
                              void* d_out, int out_size)
{
    const float* data   = (const float*)d_in[0];
    const int*   clusts = (const int*)d_in[1];
    const void*  cmask  = d_in[2];
    const int*   eidx   = (const int*)d_in[3];
    const float* W1     = (const float*)d_in[4];
    const float* b1     = (const float*)d_in[5];
    const float* W2     = (const float*)d_in[6];
    const float* b2     = (const float*)d_in[7];
    const float* W3     = (const float*)d_in[8];
    const float* b3     = (const float*)d_in[9];
    const float* Wfc    = (const float*)d_in[10];
    const float* bfc    = (const float*)d_in[11];
    float*       out    = (float*)d_out;

    const int C = in_sizes[1] / NPT;   // 256
    const int E = in_sizes[3] / 2;     // 1024
    const int maskWords = in_sizes[2] / 4;

    detect_kernel<<<1, 256>>>(eidx, (const unsigned int*)cmask, E, maskWords);
    vox_kernel<<<C, 256>>>(data, clusts, cmask);
    conv1_kernel<<<E * 8, 256>>>(eidx, W1, b1, E, C);
    conv2_kernel<<<E, 256>>>(W2, b2);
    conv3_kernel<<<E, 512>>>(W3, b3, Wfc, bfc, out);
}

// round 5
// speedup vs baseline: 1.8511x; 1.3990x over previous
#include <cuda_runtime.h>
#include <cuda_bf16.h>

#define NCLUST 256
#define NPT    128
#define NEDGE  1024
#define VS     32
#define VOXN   (VS*VS*VS)   // 32768

typedef unsigned long long ull;

// packed fp32x2 helpers (FFMA2 — only reachable via PTX)
__device__ __forceinline__ ull pk2(float lo, float hi) {
    ull r; asm("mov.b64 %0, {%1,%2};" : "=l"(r) : "f"(lo), "f"(hi)); return r;
}
__device__ __forceinline__ void fma2(ull& d, ull a, ull b) {
    asm("fma.rn.f32x2 %0, %1, %2, %0;" : "+l"(d) : "l"(a), "l"(b));
}
__device__ __forceinline__ float2 upk2(ull v) {
    float2 r; asm("mov.b64 {%0,%1}, %2;" : "=f"(r.x), "=f"(r.y) : "l"(v)); return r;
}

// Scratch (device globals)
__device__ float g_cvox[NCLUST * VOXN];              // 32 MB
__device__ float g_c1c[NCLUST * 16 * 4096];          // 67 MB  per-CLUSTER linear conv1
__device__ float g_c2[NEDGE * 32 * 8 * 8 * 8];       // 67 MB
__device__ int   g_eidx_is_i64;
__device__ int   g_mask_is_u8;

// ---------------------------------------------------------------------------
// Kernel D: dtype layout detection
// ---------------------------------------------------------------------------
__global__ void detect_kernel(const int* __restrict__ eidx_w,
                              const unsigned int* __restrict__ mask_w,
                              int E, int maskWords)
{
    __shared__ int oddNZ, bigW;
    if (threadIdx.x == 0) { oddNZ = 0; bigW = 0; }
    __syncthreads();
    for (int i = threadIdx.x; i < E; i += blockDim.x)
        if (eidx_w[2 * i + 1] != 0) atomicOr(&oddNZ, 1);
    for (int i = threadIdx.x; i < maskWords; i += blockDim.x)
        if (mask_w[i] > 1u) atomicOr(&bigW, 1);
    __syncthreads();
    if (threadIdx.x == 0) {
        g_eidx_is_i64 = (oddNZ == 0) ? 1 : 0;
        g_mask_is_u8  = bigW;
    }
}

// ---------------------------------------------------------------------------
// Kernel 0: per-cluster voxelization
// ---------------------------------------------------------------------------
__global__ __launch_bounds__(256) void vox_kernel(
    const float* __restrict__ data,
    const int* __restrict__ clusts,
    const void* __restrict__ cmask)
{
    const int c = blockIdx.x;
    const int t = threadIdx.x;

    __shared__ __align__(16) float ovy[NPT * VS];
    __shared__ __align__(16) float ovz[NPT * VS];
    __shared__ __align__(16) float sw[NPT];
    __shared__ __align__(16) float svx[NPT];
    __shared__ __align__(16) float spx[NPT], spy[NPT], spz[NPT];
    __shared__ __align__(16) float red[6 * NPT];

    const int mask_u8 = g_mask_is_u8;

    if (t < NPT) {
        int idx = clusts[c * NPT + t];
        int m;
        if (mask_u8) m = ((const unsigned char*)cmask)[c * NPT + t];
        else         m = ((const int*)cmask)[c * NPT + t];
        float x = data[idx * 5 + 0];
        float y = data[idx * 5 + 1];
        float z = data[idx * 5 + 2];
        float v = data[idx * 5 + 4];
        spx[t] = x; spy[t] = y; spz[t] = z;
        sw[t]  = m ? v : 0.0f;
        red[0*NPT + t] = m ? x :  1e9f;
        red[1*NPT + t] = m ? y :  1e9f;
        red[2*NPT + t] = m ? z :  1e9f;
        red[3*NPT + t] = m ? x : -1e9f;
        red[4*NPT + t] = m ? y : -1e9f;
        red[5*NPT + t] = m ? z : -1e9f;
    }
    __syncthreads();
    for (int s = 64; s > 0; s >>= 1) {
        if (t < s) {
            red[0*NPT + t] = fminf(red[0*NPT + t], red[0*NPT + t + s]);
            red[1*NPT + t] = fminf(red[1*NPT + t], red[1*NPT + t + s]);
            red[2*NPT + t] = fminf(red[2*NPT + t], red[2*NPT + t + s]);
            red[3*NPT + t] = fmaxf(red[3*NPT + t], red[3*NPT + t + s]);
            red[4*NPT + t] = fmaxf(red[4*NPT + t], red[4*NPT + t + s]);
            red[5*NPT + t] = fmaxf(red[5*NPT + t], red[5*NPT + t + s]);
        }
        __syncthreads();
    }
    const float minx = red[0], miny = red[NPT], minz = red[2*NPT];
    const float rx = red[3*NPT] - minx;
    const float ry = red[4*NPT] - miny;
    const float rz = red[5*NPT] - minz;
    const float mr = fmaxf(rx, fmaxf(ry, rz)) + 1.0f;
    const float gs  = 1.0f / mr;
    const float rgs = mr;
    const float ns  = 1.0f / (float)VS;

    {
        int p    = t & (NPT - 1);
        int half = t >> 7;
        float vy = (spy[p] - miny - ry * 0.5f - 0.5f) * gs + 0.5f;
        float vz = (spz[p] - minz - rz * 0.5f - 0.5f) * gs + 0.5f;
        for (int b = half * 16; b < half * 16 + 16; ++b) {
            float lo = (float)b * ns;
            float oy = fminf(vy + gs, lo + ns) - fmaxf(vy, lo);
            float oz = fminf(vz + gs, lo + ns) - fmaxf(vz, lo);
            ovy[p * VS + b] = fmaxf(oy, 0.0f) * rgs;
            ovz[p * VS + b] = fmaxf(oz, 0.0f) * rgs;
        }
        if (t < NPT)
            svx[t] = (spx[t] - minx - rx * 0.5f - 0.5f) * gs + 0.5f;
    }
    __syncthreads();

    float* outp = g_cvox + (size_t)c * VOXN;
    for (int pass = 0; pass < 4; ++pass) {
        int jk = t + pass * 256;
        int j = jk >> 5, k = jk & 31;
        float acc[VS];
#pragma unroll
        for (int i = 0; i < VS; ++i) acc[i] = 0.0f;
        for (int p = 0; p < NPT; ++p) {
            float ty = sw[p] * ovy[p * VS + j];
            if (ty != 0.0f) {
                float tz = ty * ovz[p * VS + k];
                float vx = svx[p];
#pragma unroll
                for (int i = 0; i < VS; ++i) {
                    float lo = (float)i * ns;
                    float ox = fminf(vx + gs, lo + ns) - fmaxf(vx, lo);
                    ox = fmaxf(ox, 0.0f) * rgs;
                    acc[i] += ox * tz;
                }
            }
        }
#pragma unroll
        for (int i = 0; i < VS; ++i)
            outp[i * (VS * VS) + jk] = acc[i];
    }
}

// ---------------------------------------------------------------------------
// Kernel 1: per-CLUSTER linear conv1 (1->16ch, 3^3, stride2). No bias/relu.
// grid = NCLUST*8 tiles, 256 thr. conv1(voxA+voxB) = lin(voxA)+lin(voxB).
// ---------------------------------------------------------------------------
#define SD1 20
#define SD2 340           // 20*17
#define SIN_SZ (17*SD2)   // 5780

__global__ __launch_bounds__(256, 2) void conv1c_kernel(
    const float* __restrict__ W1)
{
    __shared__ __align__(16) float s_in[SIN_SZ];
    __shared__ __align__(16) float s_w[27 * 16];   // [tap][oc]

    const int blk  = blockIdx.x;
    const int c    = blk >> 3;
    const int tile = blk & 7;
    const int tz = (tile >> 2) & 1, tyy = (tile >> 1) & 1, tx = tile & 1;
    const int t = threadIdx.x;

    const float* __restrict__ A = g_cvox + (size_t)c * VOXN;
    const int z0 = tz * 16, y0 = tyy * 16, x0 = tx * 16;

    for (int i = t; i < SIN_SZ; i += 256) s_in[i] = 0.0f;
    for (int i = t; i < 432; i += 256) {
        int oc = i / 27, tap = i % 27;
        s_w[tap * 16 + oc] = W1[i];
    }
    __syncthreads();

    for (int i = t; i < 17 * 17 * 17; i += 256) {
        int z = i / 289, r = i % 289, y = r / 17, x = r % 17;
        int gz = z0 + z, gy = y0 + y, gx = x0 + x;
        if (gz < 32 && gy < 32 && gx < 32)
            s_in[z * SD2 + y * SD1 + x] = A[(gz * 32 + gy) * 32 + gx];
    }
    __syncthreads();

    const int sg = t & 63;
    const int lx = sg & 7, ly = sg >> 3;
    const int zq = t >> 6;                 // 0..3 -> z = 2*zq + h
    const int laneoff = ly * 2 * SD1 + lx * 2;

    ull acc[2][8];
#pragma unroll
    for (int h = 0; h < 2; ++h)
#pragma unroll
        for (int m = 0; m < 8; ++m) acc[h][m] = 0ULL;

#pragma unroll
    for (int dz = 0; dz < 3; ++dz)
#pragma unroll
        for (int dy = 0; dy < 3; ++dy)
#pragma unroll
            for (int dx = 0; dx < 3; ++dx) {
                const int tap = (dz * 3 + dy) * 3 + dx;
                const ulonglong2 w01 = *(const ulonglong2*)&s_w[tap * 16];
                const ulonglong2 w23 = *(const ulonglong2*)&s_w[tap * 16 + 4];
                const ulonglong2 w45 = *(const ulonglong2*)&s_w[tap * 16 + 8];
                const ulonglong2 w67 = *(const ulonglong2*)&s_w[tap * 16 + 12];
                const int off = laneoff + dz * SD2 + dy * SD1 + dx;
#pragma unroll
                for (int h = 0; h < 2; ++h) {
                    float v = s_in[off + (zq * 2 + h) * 2 * SD2];
                    ull v2 = pk2(v, v);
                    fma2(acc[h][0], v2, w01.x);
                    fma2(acc[h][1], v2, w01.y);
                    fma2(acc[h][2], v2, w23.x);
                    fma2(acc[h][3], v2, w23.y);
                    fma2(acc[h][4], v2, w45.x);
                    fma2(acc[h][5], v2, w45.y);
                    fma2(acc[h][6], v2, w67.x);
                    fma2(acc[h][7], v2, w67.y);
                }
            }

    float* outp = g_c1c + (size_t)c * 16 * 4096;
#pragma unroll
    for (int h = 0; h < 2; ++h) {
        const int oz = tz * 8 + zq * 2 + h;
        const int oy = tyy * 8 + ly, ox = tx * 8 + lx;
        const int sp = oz * 256 + oy * 16 + ox;
#pragma unroll
        for (int m = 0; m < 8; ++m) {
            float2 p = upk2(acc[h][m]);
            outp[(2 * m)     * 4096 + sp] = p.x;
            outp[(2 * m + 1) * 4096 + sp] = p.y;
        }
    }
}

// ---------------------------------------------------------------------------
// Kernel 2: conv2 (16->32ch). grid = E*2 (z-halves), 256 thr, 3 CTAs/SM.
// Fill computes relu(linA + linB + b1) on the fly. Thread = 8oc x 4z.
// ---------------------------------------------------------------------------
#define C2PL 9                  // input planes per z-half
#define C2SZ (C2PL * SD2)       // 3060 floats

__global__ __launch_bounds__(256, 3) void conv2_kernel(
    const int* __restrict__ eidx,
    const float* __restrict__ W2,
    const float* __restrict__ b2,
    const float* __restrict__ b1,
    int E, int C)
{
    __shared__ __align__(16) float s_in[C2SZ];     // 12.2 KB
    __shared__ __align__(16) float s_w[27 * 32];   // [tap][oc]
    __shared__ __align__(16) float s_b[32];
    __shared__ __align__(16) float s_b1[16];

    const int bx = blockIdx.x;
    const int e  = bx >> 1;
    const int h  = bx & 1;       // z-half
    const int t  = threadIdx.x;

    int ca, cb;
    if (g_eidx_is_i64) { ca = eidx[2 * e]; cb = eidx[2 * (E + e)]; }
    else               { ca = eidx[e];     cb = eidx[E + e];       }
    ca = min(max(ca, 0), C - 1);
    cb = min(max(cb, 0), C - 1);

    for (int i = t; i < C2SZ; i += 256) s_in[i] = 0.0f;   // pads written once
    if (t < 32) s_b[t]  = b2[t];
    if (t < 16) s_b1[t] = b1[t];

    const int og = t >> 6;        // 0..3, uniform per warp
    const int sg = t & 63;
    const int lx = sg & 7, ly = sg >> 3;
    const int laneoff = ly * 2 * SD1 + lx * 2;

    ull acc[4][4];
#pragma unroll
    for (int m = 0; m < 4; ++m)
#pragma unroll
        for (int q = 0; q < 4; ++q) acc[m][q] = 0ULL;

    for (int ic = 0; ic < 16; ++ic) {
        __syncthreads();
        const float4* __restrict__ A4 =
            (const float4*)(g_c1c + ((size_t)ca * 16 + ic) * 4096);
        const float4* __restrict__ B4 =
            (const float4*)(g_c1c + ((size_t)cb * 16 + ic) * 4096);
        const float bias = s_b1[ic];
        for (int i4 = t; i4 < C2PL * 64; i4 += 256) {      // 576 float4
            int pl  = i4 >> 6, rem = i4 & 63;
            int z = 8 * h + pl;
            if (z < 16) {
                int y = rem >> 2, x4 = rem & 3;
                float4 a = A4[z * 64 + rem];
                float4 b = B4[z * 64 + rem];
                float4 v;
                v.x = fmaxf(a.x + b.x + bias, 0.0f);
                v.y = fmaxf(a.y + b.y + bias, 0.0f);
                v.z = fmaxf(a.z + b.z + bias, 0.0f);
                v.w = fmaxf(a.w + b.w + bias, 0.0f);
                *(float4*)&s_in[pl * SD2 + y * SD1 + x4 * 4] = v;
            }
        }
        for (int i = t; i < 27 * 32; i += 256) {
            int tap = i >> 5, oc = i & 31;
            s_w[i] = W2[(oc * 16 + ic) * 27 + tap];
        }
        __syncthreads();
#pragma unroll
        for (int dz = 0; dz < 3; ++dz)
#pragma unroll
            for (int dy = 0; dy < 3; ++dy)
#pragma unroll
                for (int dx = 0; dx < 3; ++dx) {
                    const int tap = (dz * 3 + dy) * 3 + dx;
                    const ulonglong2 wa = *(const ulonglong2*)&s_w[tap * 32 + og * 8];
                    const ulonglong2 wb = *(const ulonglong2*)&s_w[tap * 32 + og * 8 + 4];
                    const int off = laneoff + dz * SD2 + dy * SD1 + dx;
#pragma unroll
                    for (int q = 0; q < 4; ++q) {
                        float v = s_in[off + q * 2 * SD2];
                        ull v2 = pk2(v, v);
                        fma2(acc[0][q], v2, wa.x);
                        fma2(acc[1][q], v2, wa.y);
                        fma2(acc[2][q], v2, wb.x);
                        fma2(acc[3][q], v2, wb.y);
                    }
                }
    }

    float* outp = g_c2 + (size_t)e * 32 * 512;
#pragma unroll
    for (int m = 0; m < 4; ++m) {
        const int oc0 = og * 8 + 2 * m;
        const float b0 = s_b[oc0], b1v = s_b[oc0 + 1];
#pragma unroll
        for (int q = 0; q < 4; ++q) {
            float2 p = upk2(acc[m][q]);
            const int sidx = (4 * h + q) * 64 + sg;
            outp[oc0 * 512 + sidx]       = fmaxf(p.x + b0,  0.0f);
            outp[(oc0 + 1) * 512 + sidx] = fmaxf(p.y + b1v, 0.0f);
        }
    }
}

// ---------------------------------------------------------------------------
// Kernel 3: conv3 (32->64ch) + relu + mean-pool + FC. 1024 blocks x 256 thr.
// Thread = 8 oc (4 packed) x 2 spatial.
// ---------------------------------------------------------------------------
#define C3S1 12
#define C3S2 108
#define C3SZ (9*C3S2)      // 972

__global__ __launch_bounds__(256, 3) void conv3_kernel(
    const float* __restrict__ W3,
    const float* __restrict__ b3,
    const float* __restrict__ Wfc,
    const float* __restrict__ bfc,
    float* __restrict__ out)
{
    __shared__ __align__(16) float s_in[C3SZ];
    __shared__ __align__(16) float s_w[27 * 64];   // [tap][oc]
    __shared__ __align__(16) float s_pool[64 * 65];
    __shared__ __align__(16) float s_pooled[64];

    const int e = blockIdx.x;
    const int t = threadIdx.x;
    const int og  = t >> 5;    // 0..7, uniform per warp
    const int ln  = t & 31;
    const int lx = ln & 3, ly = (ln >> 2) & 3, lzl = ln >> 4;  // lzl 0..1

    for (int i = t; i < C3SZ; i += 256) s_in[i] = 0.0f;

    ull acc[4][2];
#pragma unroll
    for (int m = 0; m < 4; ++m)
#pragma unroll
        for (int q = 0; q < 2; ++q) acc[m][q] = 0ULL;

    for (int ic = 0; ic < 32; ++ic) {
        __syncthreads();
        const float4* __restrict__ src4 =
            (const float4*)(g_c2 + ((size_t)e * 32 + ic) * 512);
        if (t < 128) {
            float4 v = src4[t];
            int i = t * 4;
            int x = i & 7, y = (i >> 3) & 7, z = i >> 6;
            *(float4*)&s_in[z * C3S2 + y * C3S1 + x] = v;
        }
        for (int i = t; i < 27 * 64; i += 256) {
            int tap = i >> 6, oc = i & 63;
            s_w[i] = W3[(oc * 32 + ic) * 27 + tap];
        }
        __syncthreads();
#pragma unroll
        for (int dz = 0; dz < 3; ++dz)
#pragma unroll
            for (int dy = 0; dy < 3; ++dy)
#pragma unroll
                for (int dx = 0; dx < 3; ++dx) {
                    const int tap = (dz * 3 + dy) * 3 + dx;
                    const ulonglong2 wa = *(const ulonglong2*)&s_w[tap * 64 + og * 8];
                    const ulonglong2 wb = *(const ulonglong2*)&s_w[tap * 64 + og * 8 + 4];
                    const int boff = (2 * ly + dy) * C3S1 + 2 * lx + dx + dz * C3S2;
#pragma unroll
                    for (int q = 0; q < 2; ++q) {
                        const int lz = lzl + 2 * q;
                        float v = s_in[boff + lz * 2 * C3S2];
                        ull v2 = pk2(v, v);
                        fma2(acc[0][q], v2, wa.x);
                        fma2(acc[1][q], v2, wa.y);
                        fma2(acc[2][q], v2, wb.x);
                        fma2(acc[3][q], v2, wb.y);
                    }
                }
    }
    __syncthreads();
#pragma unroll
    for (int q = 0; q < 2; ++q) {
        const int s = (lzl + 2 * q) * 16 + ly * 4 + lx;
#pragma unroll
        for (int m = 0; m < 4; ++m) {
            float2 p = upk2(acc[m][q]);
            const int oc0 = og * 8 + 2 * m;
            s_pool[s * 65 + oc0]     = fmaxf(p.x + __ldg(&b3[oc0]),     0.0f);
            s_pool[s * 65 + oc0 + 1] = fmaxf(p.y + __ldg(&b3[oc0 + 1]), 0.0f);
        }
    }
    __syncthreads();
    if (t < 64) {
        float sum = 0.0f;
#pragma unroll 8
        for (int sp = 0; sp < 64; ++sp) sum += s_pool[sp * 65 + t];
        s_pooled[t] = sum * (1.0f / 64.0f);
    }
    __syncthreads();
    if (t < 64) {
        float r = bfc[t];
#pragma unroll 8
        for (int ic = 0; ic < 64; ++ic)
            r += s_pooled[ic] * __ldg(&Wfc[ic * 64 + t]);
        out[e * 64 + t] = r;
    }
}

// ---------------------------------------------------------------------------
extern "C" void kernel_launch(void* const* d_in, const int* in_sizes, int n_in,
                              void* d_out, int out_size)
{
    const float* data   = (const float*)d_in[0];
    const int*   clusts = (const int*)d_in[1];
    const void*  cmask  = d_in[2];
    const int*   eidx   = (const int*)d_in[3];
    const float* W1     = (const float*)d_in[4];
    const float* b1     = (const float*)d_in[5];
    const float* W2     = (const float*)d_in[6];
    const float* b2     = (const float*)d_in[7];
    const float* W3     = (const float*)d_in[8];
    const float* b3     = (const float*)d_in[9];
    const float* Wfc    = (const float*)d_in[10];
    const float* bfc    = (const float*)d_in[11];
    float*       out    = (float*)d_out;

    const int C = in_sizes[1] / NPT;   // 256
    const int E = in_sizes[3] / 2;     // 1024
    const int maskWords = in_sizes[2] / 4;

    detect_kernel<<<1, 256>>>(eidx, (const unsigned int*)cmask, E, maskWords);
    vox_kernel<<<C, 256>>>(data, clusts, cmask);
    conv1c_kernel<<<C * 8, 256>>>(W1);
    conv2_kernel<<<E * 2, 256>>>(eidx, W2, b2, b1, E, C);
    conv3_kernel<<<E, 256>>>(W3, b3, Wfc, bfc, out);
}